// round 7
// baseline (speedup 1.0000x reference)
#include <cuda_runtime.h>
#include <cstdint>

#define NTAGS 24
#define SEQ   512
#define BATCH 2048
#define WPB   4
#define THREADS (WPB * 32)
#define CH    8
#define NCHUNK (SEQ / CH)
#define FULL  0xffffffffu

typedef unsigned long long u64;

__device__ float    g_part[BATCH];
__device__ unsigned g_ctr = 0;

static __device__ __forceinline__ u64 pk2(float lo, float hi) {
    u64 r; asm("mov.b64 %0, {%1, %2};" : "=l"(r) : "f"(lo), "f"(hi)); return r;
}
static __device__ __forceinline__ void un2(u64 v, float& lo, float& hi) {
    asm("mov.b64 {%0, %1}, %2;" : "=f"(lo), "=f"(hi) : "l"(v));
}
static __device__ __forceinline__ u64 fma2(u64 a, u64 b, u64 c) {
    u64 d; asm("fma.rn.f32x2 %0, %1, %2, %3;" : "=l"(d) : "l"(a), "l"(b), "l"(c)); return d;
}
static __device__ __forceinline__ u64 mul2(u64 a, u64 b) {
    u64 d; asm("mul.rn.f32x2 %0, %1, %2;" : "=l"(d) : "l"(a), "l"(b)); return d;
}
static __device__ __forceinline__ u64 add2(u64 a, u64 b) {
    u64 d; asm("add.rn.f32x2 %0, %1, %2;" : "=l"(d) : "l"(a), "l"(b)); return d;
}
static __device__ __forceinline__ unsigned cmprs(int4 a, int4 b) {
    unsigned r = 0;
    r |= (a.x != 0) ? 1u   : 0u;  r |= (a.y != 0) ? 2u   : 0u;
    r |= (a.z != 0) ? 4u   : 0u;  r |= (a.w != 0) ? 8u   : 0u;
    r |= (b.x != 0) ? 16u  : 0u;  r |= (b.y != 0) ? 32u  : 0u;
    r |= (b.z != 0) ? 64u  : 0u;  r |= (b.w != 0) ? 128u : 0u;
    return r;
}

__global__ void __launch_bounds__(THREADS) crf_fwd_kernel(
    const float* __restrict__ emissions,
    const int*   __restrict__ tags,
    const int*   __restrict__ mask,
    const float* __restrict__ trans,
    float*       __restrict__ out)
{
    __shared__ float s_traw[NTAGS * NTAGS];
    __shared__ __align__(16) float s_p[WPB][2][2][32];  // [warp][elem][slot][lane]
    __shared__ int s_done;
    __shared__ float s_red[THREADS];

    const int tid  = threadIdx.x;
    const int lane = tid & 31;
    const int wid  = tid >> 5;
    const int eA   = (blockIdx.x * WPB + wid) * 2;   // two elements per warp

    for (int i = tid; i < NTAGS * NTAGS; i += THREADS) s_traw[i] = trans[i];
    __syncthreads();

    const bool act = (lane < NTAGS);
    const bool isg = (lane >= NTAGS);
    const int  ggk = isg ? (lane - NTAGS) : 0;

    const float* emA = emissions + (size_t)eA * (SEQ * NTAGS);
    const float* emB = emA + (SEQ * NTAGS);
    const int*   tgA = tags + (size_t)eA * SEQ;
    const int*   tgB = tgA + SEQ;
    const int*   mkA = mask + (size_t)eA * SEQ;
    const int*   mkB = mkA + SEQ;

#define PRE1(EM, C, EB)                                                       \
    do {                                                                      \
        const float* _ep = (EM) + (size_t)(C) * (CH * NTAGS) + lane;          \
        _Pragma("unroll")                                                     \
        for (int _k = 0; _k < CH; _k++)                                       \
            EB[_k] = act ? _ep[_k * NTAGS] : -1e30f;                          \
    } while (0)

    // early independent loads
    int4 maA = *(const int4*)(mkA), mbA = *(const int4*)(mkA + 4);
    int4 maB = *(const int4*)(mkB), mbB = *(const int4*)(mkB + 4);
    int  ttA = tgA[ggk], ttB = tgB[ggk];

    float ebA0[CH], ebA1[CH], ebB0[CH], ebB1[CH];
    PRE1(emA, 0, ebA0); PRE1(emB, 0, ebB0);
    PRE1(emA, 1, ebA1); PRE1(emB, 1, ebB1);

    // packed expT columns, normalized by R = max column sum
    u64 tc[12];
#pragma unroll
    for (int k = 0; k < 12; k++) {
        float a = act ? __expf(trans[(2 * k)     * NTAGS + lane]) : 0.f;
        float c = act ? __expf(trans[(2 * k + 1) * NTAGS + lane]) : 0.f;
        tc[k] = pk2(a, c);
    }
    u64 cs2 = tc[0];
#pragma unroll
    for (int k = 1; k < 12; k++) cs2 = add2(cs2, tc[k]);
    float cl, chh; un2(cs2, cl, chh);
    float R = cl + chh;
#pragma unroll
    for (int o = 16; o; o >>= 1)
        R = fmaxf(R, __shfl_xor_sync(FULL, R, o));
    const float lnR = __logf(R);
    const u64 rin2 = pk2(1.0f / R, 1.0f / R);
#pragma unroll
    for (int k = 0; k < 12; k++) tc[k] = mul2(tc[k], rin2);

    unsigned mbitsA = cmprs(maA, mbA), mbitsB = cmprs(maB, mbB);
    int ntotA = __popc(mbitsA & 0xFEu), ntotB = __popc(mbitsB & 0xFEu);

    float exA[CH], exB[CH];
#pragma unroll
    for (int k = 0; k < CH; k++) { exA[k] = __expf(ebA0[k]); exB[k] = __expf(ebB0[k]); }

    // init both elements
    float MA = exA[0], MB = exB[0];
#pragma unroll
    for (int o = 16; o; o >>= 1) {
        MA = fmaxf(MA, __shfl_xor_sync(FULL, MA, o));
        MB = fmaxf(MB, __shfl_xor_sync(FULL, MB, o));
    }
    float pA = exA[0] * __fdividef(1.0f, MA);
    float pB = exB[0] * __fdividef(1.0f, MB);
    float CcA = __logf(MA), CcB = __logf(MB);

    int   tcA = 0, tcB = 0;   // tag carries
    float goldA = 0.f, goldB = 0.f;

    // dual matvec: both elements per step, interleaved FFMA2 trees
#define MATV2(K, EXA, EXB, UA, UB)                                            \
    float* _ba = &s_p[wid][0][(K) & 1][0];                                    \
    float* _bb = &s_p[wid][1][(K) & 1][0];                                    \
    _ba[lane] = pA;                                                           \
    _bb[lane] = pB;                                                           \
    asm volatile("" ::: "memory");                                            \
    const ulonglong2* _qa = (const ulonglong2*)_ba;                           \
    const ulonglong2* _qb = (const ulonglong2*)_bb;                           \
    ulonglong2 qa0 = _qa[0], qa1 = _qa[1], qa2 = _qa[2];                      \
    ulonglong2 qb0 = _qb[0], qb1 = _qb[1], qb2 = _qb[2];                      \
    u64 xa0 = mul2(qa0.x, tc[0]);                                             \
    u64 xb0 = mul2(qb0.x, tc[0]);                                             \
    u64 xa1 = mul2(qa0.y, tc[1]);                                             \
    u64 xb1 = mul2(qb0.y, tc[1]);                                             \
    u64 xa2 = mul2(qa1.x, tc[2]);                                             \
    u64 xb2 = mul2(qb1.x, tc[2]);                                             \
    u64 xa3 = mul2(qa1.y, tc[3]);                                             \
    u64 xb3 = mul2(qb1.y, tc[3]);                                             \
    xa0 = fma2(qa2.x, tc[4], xa0);                                            \
    xb0 = fma2(qb2.x, tc[4], xb0);                                            \
    xa1 = fma2(qa2.y, tc[5], xa1);                                            \
    xb1 = fma2(qb2.y, tc[5], xb1);                                            \
    ulonglong2 qa3 = _qa[3], qa4 = _qa[4], qa5 = _qa[5];                      \
    ulonglong2 qb3 = _qb[3], qb4 = _qb[4], qb5 = _qb[5];                      \
    xa2 = fma2(qa3.x, tc[6], xa2);                                            \
    xb2 = fma2(qb3.x, tc[6], xb2);                                            \
    xa3 = fma2(qa3.y, tc[7], xa3);                                            \
    xb3 = fma2(qb3.y, tc[7], xb3);                                            \
    xa0 = fma2(qa4.x, tc[8], xa0);                                            \
    xb0 = fma2(qb4.x, tc[8], xb0);                                            \
    xa1 = fma2(qa4.y, tc[9], xa1);                                            \
    xb1 = fma2(qb4.y, tc[9], xb1);                                            \
    xa2 = fma2(qa5.x, tc[10], xa2);                                           \
    xb2 = fma2(qb5.x, tc[10], xb2);                                           \
    xa3 = fma2(qa5.y, tc[11], xa3);                                           \
    xb3 = fma2(qb5.y, tc[11], xb3);                                           \
    u64 sa2 = add2(add2(xa0, xa1), add2(xa2, xa3));                           \
    u64 sb2 = add2(add2(xb0, xb1), add2(xb2, xb3));                           \
    float sal, sah, sbl, sbh;                                                 \
    un2(sa2, sal, sah);                                                       \
    un2(sb2, sbl, sbh);                                                       \
    const float UA = (sal + sah) * (EXA);                                     \
    const float UB = (sbl + sbh) * (EXB);

#define RESCALE2()                                                            \
    do {                                                                      \
        float _ma = pA, _mb = pB;                                             \
        _Pragma("unroll")                                                     \
        for (int _o = 16; _o; _o >>= 1) {                                     \
            _ma = fmaxf(_ma, __shfl_xor_sync(FULL, _ma, _o));                 \
            _mb = fmaxf(_mb, __shfl_xor_sync(FULL, _mb, _o));                 \
        }                                                                     \
        pA *= __fdividef(1.0f, _ma);                                          \
        pB *= __fdividef(1.0f, _mb);                                          \
        CcA += __logf(_ma);                                                   \
        CcB += __logf(_mb);                                                   \
    } while (0)

#define CBODY(C, K0, PA, PB, CA, CB, PRE_ON, NXT_ON, RSFLAG, FIRST)           \
    do {                                                                      \
        const float geA = emA[((C) * CH + ggk) * NTAGS + ttA];                \
        const float geB = emB[((C) * CH + ggk) * NTAGS + ttB];                \
        int ttA_nx = 0, ttB_nx = 0;                                           \
        int4 naA = make_int4(0,0,0,0), nbA = naA, naB = naA, nbB = naA;       \
        if (NXT_ON) {                                                         \
            ttA_nx = tgA[((C) + 1) * CH + ggk];                               \
            ttB_nx = tgB[((C) + 1) * CH + ggk];                               \
            naA = *(const int4*)(mkA + ((C) + 1) * CH);                       \
            nbA = *(const int4*)(mkA + ((C) + 1) * CH + 4);                   \
            naB = *(const int4*)(mkB + ((C) + 1) * CH);                       \
            nbB = *(const int4*)(mkB + ((C) + 1) * CH + 4);                   \
        }                                                                     \
        if (PRE_ON) { PRE1(emA, (C) + 2, PA); PRE1(emB, (C) + 2, PB); }       \
        if ((mbitsA & mbitsB) == 0xFFu) {                                     \
            _Pragma("unroll")                                                 \
            for (int k = K0; k < CH; k++) {                                   \
                MATV2(k, exA[k], exB[k], _ua, _ub);                           \
                pA = _ua; pB = _ub;                                           \
            }                                                                 \
        } else {                                                              \
            _Pragma("unroll")                                                 \
            for (int k = K0; k < CH; k++) {                                   \
                MATV2(k, exA[k], exB[k], _ua, _ub);                           \
                pA = ((mbitsA >> k) & 1u) ? _ua : pA;                         \
                pB = ((mbitsB >> k) & 1u) ? _ub : pB;                         \
            }                                                                 \
        }                                                                     \
        int tpA = __shfl_up_sync(FULL, ttA, 1);                               \
        int tpB = __shfl_up_sync(FULL, ttB, 1);                               \
        tpA = (lane == NTAGS) ? tcA : tpA;                                    \
        tpB = (lane == NTAGS) ? tcB : tpB;                                    \
        float gtA = s_traw[tpA * NTAGS + ttA];                                \
        float gtB = s_traw[tpB * NTAGS + ttB];                                \
        if (FIRST) {                                                          \
            gtA = (lane == NTAGS) ? 0.f : gtA;                                \
            gtB = (lane == NTAGS) ? 0.f : gtB;                                \
        }                                                                     \
        goldA += (isg && ((mbitsA >> ggk) & 1u)) ? (geA + gtA) : 0.f;         \
        goldB += (isg && ((mbitsB >> ggk) & 1u)) ? (geB + gtB) : 0.f;         \
        tcA = __shfl_sync(FULL, ttA, 31);                                     \
        tcB = __shfl_sync(FULL, ttB, 31);                                     \
        ttA = ttA_nx; ttB = ttB_nx;                                           \
        if (RSFLAG) RESCALE2();                                               \
        if (NXT_ON) {                                                         \
            _Pragma("unroll")                                                 \
            for (int k = 0; k < CH; k++) {                                    \
                exA[k] = __expf(CA[k]);                                       \
                exB[k] = __expf(CB[k]);                                       \
            }                                                                 \
            mbitsA = cmprs(naA, nbA);                                         \
            mbitsB = cmprs(naB, nbB);                                         \
            ntotA += __popc(mbitsA);                                          \
            ntotB += __popc(mbitsB);                                          \
        }                                                                     \
    } while (0)

    CBODY(0, 1, ebA0, ebB0, ebA1, ebB1, true, true, false, true);

    for (int c = 1; c <= 59; c += 2) {
        CBODY(c,     0, ebA1, ebB1, ebA0, ebB0, true, true, ((c & 3) == 3), false);
        CBODY(c + 1, 0, ebA0, ebB0, ebA1, ebB1, true, true, false,          false);
    }

    CBODY(61, 0, ebA1, ebB1, ebA0, ebB0, true,  true,  false, false);
    CBODY(62, 0, ebA0, ebB0, ebA1, ebB1, false, true,  false, false);
    CBODY(63, 0, ebA1, ebB1, ebA0, ebB0, false, false, true,  false);

    float zsA = pA, zsB = pB;
#pragma unroll
    for (int o = 16; o; o >>= 1) {
        zsA += __shfl_xor_sync(FULL, zsA, o);
        zsB += __shfl_xor_sync(FULL, zsB, o);
    }
    const float ldA = CcA + (float)ntotA * lnR + __logf(zsA);
    const float ldB = CcB + (float)ntotB * lnR + __logf(zsB);

    goldA += __shfl_xor_sync(FULL, goldA, 1);
    goldB += __shfl_xor_sync(FULL, goldB, 1);
    goldA += __shfl_xor_sync(FULL, goldA, 2);
    goldB += __shfl_xor_sync(FULL, goldB, 2);
    goldA += __shfl_xor_sync(FULL, goldA, 4);
    goldB += __shfl_xor_sync(FULL, goldB, 4);
    const float gA = __shfl_sync(FULL, goldA, NTAGS);
    const float gB = __shfl_sync(FULL, goldB, NTAGS);

    if (lane == 0) {
        g_part[eA]     = ldA - gA;
        g_part[eA + 1] = ldB - gB;
    }

    __syncthreads();
    if (tid == 0) {
        __threadfence();
        unsigned prev = atomicInc(&g_ctr, gridDim.x - 1);
        s_done = (prev == gridDim.x - 1);
    }
    __syncthreads();
    if (s_done) {
        float v = 0.0f;
        for (int i = tid; i < BATCH; i += THREADS) v += g_part[i];
        s_red[tid] = v;
        __syncthreads();
#pragma unroll
        for (int s = THREADS / 2; s; s >>= 1) {
            if (tid < s) s_red[tid] += s_red[tid + s];
            __syncthreads();
        }
        if (tid == 0) out[0] = s_red[0] * (1.0f / BATCH);
    }
}

extern "C" void kernel_launch(void* const* d_in, const int* in_sizes, int n_in,
                              void* d_out, int out_size)
{
    const float* emissions = (const float*)d_in[0];
    const int*   tags      = (const int*)d_in[1];
    const int*   mask      = (const int*)d_in[2];
    const float* trans     = (const float*)d_in[3];

    crf_fwd_kernel<<<BATCH / (2 * WPB), THREADS>>>(
        emissions, tags, mask, trans, (float*)d_out);
}